// round 11
// baseline (speedup 1.0000x reference)
#include <cuda_runtime.h>
#include <cuda_fp16.h>
#include <cstdint>
#include <math.h>

// ---------------- problem constants ----------------
static constexpr int BATCH  = 64;
static constexpr int NA     = 8192;     // i (mask rows)
static constexpr int NB     = 8192;     // j (mask cols)
static constexpr int NCHUNK = 4096;     // 64 i-tiles x 64 j-chunks (128x128 each)
static constexpr int NCTA   = 148;
static constexpr int NTHREADS = 256;

// smem layout
static constexpr int RAW_PITCH = 544;                   // 512B + 32B pad
static constexpr int RAW_SZ    = 128 * RAW_PITCH;       // 69632 (single buffer)
static constexpr int PITCH     = 272;                   // fp16 tile pitch (17x16B)
static constexpr int A_BASE    = RAW_SZ;                // 69632
static constexpr int T_STAGE   = 128 * PITCH;           // 34816
static constexpr int B_BASE    = A_BASE + 2 * T_STAGE;  // 139264
static constexpr int ACC_OFF   = B_BASE + 2 * T_STAGE;  // 208896
static constexpr int SMEM_BYTES = ACC_OFF + 512;        // 209408
static constexpr int CA_PITCH  = 132;                   // floats (2*64*132*4 = 67584 <= RAW_SZ)

// ---------------- device scratch ----------------
__device__ __half g_B16[NB * 128];     // row j: [cb(b) | sb(b)] fp16
__device__ float  g_caf[BATCH * NA];
__device__ float  g_saf[BATCH * NA];
__device__ float  g_real[BATCH];
__device__ float  g_imag[BATCH];
__device__ unsigned int g_npairs;

// ---------------- helpers ----------------
__device__ __forceinline__ uint32_t smem_u32(const void* p) {
    uint32_t a;
    asm("{ .reg .u64 t; cvta.to.shared.u64 t, %1; cvt.u32.u64 %0, t; }" : "=r"(a) : "l"(p));
    return a;
}
__device__ __forceinline__ void cp_async16(uint32_t s, const void* g) {
    asm volatile("cp.async.cg.shared.global [%0], [%1], 16;" :: "r"(s), "l"(g) : "memory");
}
#define CP_COMMIT()  asm volatile("cp.async.commit_group;" ::: "memory")
#define CP_WAIT0()   asm volatile("cp.async.wait_group 0;" ::: "memory")

__device__ __forceinline__ void lds128(uint4& v, uint32_t a) {
    asm volatile("ld.shared.v4.b32 {%0,%1,%2,%3}, [%4];"
        : "=r"(v.x), "=r"(v.y), "=r"(v.z), "=r"(v.w) : "r"(a));
}
__device__ __forceinline__ void sts128(uint32_t a, uint32_t x, uint32_t y, uint32_t z, uint32_t w) {
    asm volatile("st.shared.v4.b32 [%0], {%1,%2,%3,%4};"
        :: "r"(a), "r"(x), "r"(y), "r"(z), "r"(w) : "memory");
}

#define LDSM_X4(r, addr) \
    asm volatile("ldmatrix.sync.aligned.m8n8.x4.shared.b16 {%0,%1,%2,%3}, [%4];" \
        : "=r"((r)[0]), "=r"((r)[1]), "=r"((r)[2]), "=r"((r)[3]) : "r"(addr))
#define LDSM_X4_T(r, addr) \
    asm volatile("ldmatrix.sync.aligned.m8n8.x4.trans.shared.b16 {%0,%1,%2,%3}, [%4];" \
        : "=r"((r)[0]), "=r"((r)[1]), "=r"((r)[2]), "=r"((r)[3]) : "r"(addr))

__device__ __forceinline__ void mma_16816(float* d, const uint32_t* a, uint32_t b0, uint32_t b1) {
    asm volatile(
        "mma.sync.aligned.m16n8k16.row.col.f32.f16.f16.f32 "
        "{%0,%1,%2,%3}, {%4,%5,%6,%7}, {%8,%9}, {%0,%1,%2,%3};"
        : "+f"(d[0]), "+f"(d[1]), "+f"(d[2]), "+f"(d[3])
        : "r"(a[0]), "r"(a[1]), "r"(a[2]), "r"(a[3]), "r"(b0), "r"(b1));
}
__device__ __forceinline__ uint32_t pk(uint32_t a, uint32_t b) {  // {0,1}x2 -> half2, exact
    return a * 0x3C00u + b * 0x3C000000u;
}

// ---------------- prep (4 parts, for ncu launch alignment) ----------------
__global__ void plv_prep(const float* __restrict__ pa, const float* __restrict__ pb, int part) {
    const int idx = part * (BATCH * NA / 4) + blockIdx.x * blockDim.x + threadIdx.x;
    float s, c;
    // a-side: coalesced read & write
    sincosf(pa[idx], &s, &c);
    g_caf[idx] = c;
    g_saf[idx] = s;
    // b-side: j-major mapping -> coalesced g_B16 writes (pb reads strided, L2-served)
    const int j  = idx >> 6;
    const int b2 = idx & 63;
    sincosf(pb[(size_t)b2 * NB + j], &s, &c);
    g_B16[(size_t)j * 128 + b2]      = __float2half_rn(c);
    g_B16[(size_t)j * 128 + 64 + b2] = __float2half_rn(s);
}

__global__ void plv_zero() {
    if (threadIdx.x < BATCH) { g_real[threadIdx.x] = 0.0f; g_imag[threadIdx.x] = 0.0f; }
    if (threadIdx.x == BATCH) g_npairs = 0u;
}

// ---------------- main: persistent 148 CTAs, static chunk partition ----------------
__global__ void __launch_bounds__(NTHREADS, 1) plv_main(const int* __restrict__ mask) {
    extern __shared__ char smem_raw[];
    const uint32_t sb = smem_u32(smem_raw);

    const int tid  = threadIdx.x;
    const int wid  = tid >> 5;
    const int lane = tid & 31;
    const int wm   = wid >> 1;          // 0..3: 32 i-rows
    const int wn   = wid & 1;           // 0..1: cos/sin 64-col half
    const int tc   = (lane & 3) * 2;

    const int c0 = (int)(((long long)blockIdx.x * NCHUNK) / NCTA);
    const int c1 = (int)(((long long)(blockIdx.x + 1) * NCHUNK) / NCTA);

    unsigned int msum = 0;
    float acc[2][8][4];
#pragma unroll
    for (int i = 0; i < 2; ++i)
#pragma unroll
        for (int j = 0; j < 8; ++j)
#pragma unroll
            for (int r = 0; r < 4; ++r) acc[i][j][r] = 0.0f;

    // ---- issue chunk: raw mask (64KB, single buf) + B trig (32KB, stage s) ----
    auto issue = [&](int c, int s) {
        const int i0 = (c >> 6) * 128;
        const int j0 = (c & 63) * 128;
        const int* src = mask + (size_t)i0 * NB + j0;
#pragma unroll
        for (int it = 0; it < 16; ++it) {
            const int idx = tid + it * 256;
            const int k = idx >> 5;
            const int g = idx & 31;
            cp_async16(sb + (uint32_t)k * RAW_PITCH + (uint32_t)g * 16,
                       src + (size_t)k * NB + g * 4);
        }
        const uint32_t bdst = sb + B_BASE + (uint32_t)s * T_STAGE;
#pragma unroll
        for (int it = 0; it < 8; ++it) {
            const int idx = tid + it * 256;
            const int k = idx >> 4;
            const int g = idx & 15;
            cp_async16(bdst + (uint32_t)k * PITCH + (uint32_t)g * 16,
                       (const char*)g_B16 + ((size_t)(j0 + k) * 128 + (size_t)g * 8) * 2);
        }
        CP_COMMIT();
    };

    // ---- convert raw int32 tile -> fp16 A tile (stage s) ----
    const int cr = tid >> 1;            // row 0..127
    const int ch = tid & 1;             // col half (64 cols)
    auto conv = [&](int s) {
        const uint32_t src = sb + (uint32_t)cr * RAW_PITCH + (uint32_t)ch * 256;
        const uint32_t dst = sb + A_BASE + (uint32_t)s * T_STAGE
                           + (uint32_t)cr * PITCH + (uint32_t)ch * 128;
#pragma unroll
        for (int q = 0; q < 4; ++q) {
            uint4 v0, v1, v2, v3;
            lds128(v0, src + q * 64);
            lds128(v1, src + q * 64 + 16);
            lds128(v2, src + q * 64 + 32);
            lds128(v3, src + q * 64 + 48);
            msum += v0.x + v0.y + v0.z + v0.w + v1.x + v1.y + v1.z + v1.w
                  + v2.x + v2.y + v2.z + v2.w + v3.x + v3.y + v3.z + v3.w;
            sts128(dst + q * 32,      pk(v0.x, v0.y), pk(v0.z, v0.w), pk(v1.x, v1.y), pk(v1.z, v1.w));
            sts128(dst + q * 32 + 16, pk(v2.x, v2.y), pk(v2.z, v2.w), pk(v3.x, v3.y), pk(v3.z, v3.w));
        }
    };

    // ---- compute (A via ldmatrix, B via ldmatrix.trans) ----
    auto compute = [&](int s) {
        const uint32_t aAddr = sb + A_BASE + (uint32_t)s * T_STAGE
                             + (uint32_t)(wm * 32 + (lane & 15)) * PITCH + (uint32_t)(lane >> 4) * 16;
        const uint32_t bAddr = sb + B_BASE + (uint32_t)s * T_STAGE + (uint32_t)(wn * 128)
                             + (uint32_t)(lane & 15) * PITCH + (uint32_t)(lane >> 4) * 16;
#pragma unroll
        for (int kb = 0; kb < 8; ++kb) {
            uint32_t a0[4], a1[4];
            LDSM_X4(a0, aAddr + (uint32_t)kb * 32);
            LDSM_X4(a1, aAddr + 16u * PITCH + (uint32_t)kb * 32);
            const uint32_t bk = bAddr + (uint32_t)(kb * 16) * PITCH;
#pragma unroll
            for (int nj = 0; nj < 4; ++nj) {
                uint32_t bfr[4];
                LDSM_X4_T(bfr, bk + (uint32_t)nj * 32);
                mma_16816(acc[0][nj * 2 + 0], a0, bfr[0], bfr[1]);
                mma_16816(acc[0][nj * 2 + 1], a0, bfr[2], bfr[3]);
                mma_16816(acc[1][nj * 2 + 0], a1, bfr[0], bfr[1]);
                mma_16816(acc[1][nj * 2 + 1], a1, bfr[2], bfr[3]);
            }
        }
    };

    // ---- per-i-tile flush: fused ca/sa epilogue + global atomics + acc reset ----
    float* cas    = reinterpret_cast<float*>(smem_raw);            // reuses raw region
    float* sas    = cas + 64 * CA_PITCH;
    float* real_s = reinterpret_cast<float*>(smem_raw + ACC_OFF);
    float* imag_s = real_s + 64;
    auto flush = [&](int itile) {
        const int i0 = itile * 128;
        if (tid < 64) { real_s[tid] = 0.0f; imag_s[tid] = 0.0f; }
#pragma unroll
        for (int it = 0; it < 8; ++it) {
            const int idx = tid + it * 256;
            const int r = idx >> 5;
            const int q = idx & 31;
            *reinterpret_cast<float4*>(&cas[r * CA_PITCH + q * 4]) =
                *reinterpret_cast<const float4*>(&g_caf[(size_t)r * NA + i0 + q * 4]);
            *reinterpret_cast<float4*>(&sas[r * CA_PITCH + q * 4]) =
                *reinterpret_cast<const float4*>(&g_saf[(size_t)r * NA + i0 + q * 4]);
        }
        __syncthreads();
        const int il0 = wm * 32 + (lane >> 2);
#pragma unroll
        for (int nj2 = 0; nj2 < 8; ++nj2) {
#pragma unroll
            for (int h2 = 0; h2 < 2; ++h2) {
                const int b = nj2 * 8 + tc + h2;
                float rsum = 0.0f, isum = 0.0f;
#pragma unroll
                for (int mi = 0; mi < 2; ++mi) {
#pragma unroll
                    for (int hr = 0; hr < 2; ++hr) {
                        const int il = il0 + mi * 16 + hr * 8;
                        const float X  = acc[mi][nj2][hr * 2 + h2];
                        const float ca = cas[b * CA_PITCH + il];
                        const float sa = sas[b * CA_PITCH + il];
                        if (wn == 0) { rsum = fmaf(ca, X, rsum); isum = fmaf(sa, X, isum); }
                        else         { rsum = fmaf(sa, X, rsum); isum = fmaf(-ca, X, isum); }
                    }
                }
                atomicAdd(&real_s[b], rsum);
                atomicAdd(&imag_s[b], isum);
            }
        }
        __syncthreads();
        if (tid < 64) {
            atomicAdd(&g_real[tid], real_s[tid]);
            atomicAdd(&g_imag[tid], imag_s[tid]);
        }
#pragma unroll
        for (int i = 0; i < 2; ++i)
#pragma unroll
            for (int j = 0; j < 8; ++j)
#pragma unroll
                for (int r = 0; r < 4; ++r) acc[i][j][r] = 0.0f;
    };

    // ---------------- chunk runs ----------------
    int c = c0;
    while (c < c1) {
        const int itile = c >> 6;
        const int cend  = min(c1, (itile + 1) * 64);
        // prologue for this run
        issue(c, 0);
        CP_WAIT0();
        __syncthreads();
        for (int k = 0; c + k < cend; ++k) {
            const int s = k & 1;
            conv(s);                         // raw -> A[s]
            __syncthreads();                 // conv visible; raw free
            if (c + k + 1 < cend) issue(c + k + 1, s ^ 1);
            compute(s);                      // copies fly under compute
            CP_WAIT0();
            __syncthreads();
        }
        flush(itile);
        c = cend;
    }

    // ---- n_pairs reduce (conv counted every element once) ----
#pragma unroll
    for (int o = 16; o; o >>= 1) msum += __shfl_down_sync(0xFFFFFFFFu, msum, o);
    if (lane == 0) atomicAdd(&g_npairs, msum);
}

// ---------------- final ----------------
__global__ void plv_final(float* __restrict__ out) {
    const int b = threadIdx.x;
    if (b < BATCH) {
        const float np = fmaxf((float)g_npairs, 1.0f);
        const float r = g_real[b], i = g_imag[b];
        out[b] = sqrtf(r * r + i * i) / np;
    }
}

// ---------------- launch (7 launches: ncu -s 5 -c 1 captures #6 = plv_main) ----------------
extern "C" void kernel_launch(void* const* d_in, const int* in_sizes, int n_in,
                              void* d_out, int out_size) {
    (void)in_sizes; (void)n_in; (void)out_size;
    const float* pa = (const float*)d_in[0];
    const float* pb = (const float*)d_in[1];
    const int* mask = (const int*)d_in[2];
    float* out      = (float*)d_out;

    cudaFuncSetAttribute(plv_main, cudaFuncAttributeMaxDynamicSharedMemorySize, SMEM_BYTES);

    plv_prep<<<512, 256>>>(pa, pb, 0);   // 1
    plv_prep<<<512, 256>>>(pa, pb, 1);   // 2
    plv_prep<<<512, 256>>>(pa, pb, 2);   // 3
    plv_prep<<<512, 256>>>(pa, pb, 3);   // 4
    plv_zero<<<1, 128>>>();              // 5
    plv_main<<<NCTA, NTHREADS, SMEM_BYTES>>>(mask);   // 6  <- ncu target
    plv_final<<<1, 64>>>(out);           // 7
}

// round 12
// speedup vs baseline: 1.8277x; 1.8277x over previous
#include <cuda_runtime.h>
#include <cuda_fp16.h>
#include <cstdint>
#include <math.h>

// ---------------- problem constants ----------------
static constexpr int BATCH  = 64;
static constexpr int NA     = 8192;                  // i dimension (mask rows, GEMM K)
static constexpr int NB     = 8192;                  // j dimension (mask cols, GEMM N)
static constexpr int NJT    = 64;                    // j tiles of 128
static constexpr int NKC    = 64;                    // k chunks of 128
static constexpr int NCHUNK = NJT * NKC;             // 4096
static constexpr int NCTA   = 148;                   // persistent grid = #SMs
static constexpr int NTHREADS = 256;

// SMEM tiles, padded pitch 136 halves = 272 B (17 x 16B -> conflict-free LDSM)
static constexpr int PITCH_B  = 272;
static constexpr int TILE_BYTES = 128 * PITCH_B;     // 34816
static constexpr int STAGE    = 2 * TILE_BYTES;      // A + B = 69632
static constexpr int ACC_OFF  = 2 * STAGE;           // 139264
static constexpr int SMEM_BYTES = ACC_OFF + 1024;
static constexpr int CB_PITCH = 132;                 // floats

// ---------------- device scratch ----------------
__device__ __half g_A[2 * BATCH * NA];   // rows 0..63 = cos(a), 64..127 = sin(a); K-major
__device__ float  g_cb[BATCH * NB];
__device__ float  g_sb[BATCH * NB];
__device__ float  g_real[BATCH];
__device__ float  g_imag[BATCH];
__device__ unsigned int g_npairs;

// ---------------- helpers ----------------
__device__ __forceinline__ uint32_t smem_u32(const void* p) {
    uint32_t a;
    asm("{ .reg .u64 t; cvta.to.shared.u64 t, %1; cvt.u32.u64 %0, t; }" : "=r"(a) : "l"(p));
    return a;
}
__device__ __forceinline__ void cp_async16(uint32_t s, const void* g) {
    asm volatile("cp.async.cg.shared.global [%0], [%1], 16;" :: "r"(s), "l"(g) : "memory");
}
#define CP_COMMIT()  asm volatile("cp.async.commit_group;" ::: "memory")
#define CP_WAIT0()   asm volatile("cp.async.wait_group 0;" ::: "memory")

#define LDSM_X4(r, addr) \
    asm volatile("ldmatrix.sync.aligned.m8n8.x4.shared.b16 {%0,%1,%2,%3}, [%4];" \
        : "=r"((r)[0]), "=r"((r)[1]), "=r"((r)[2]), "=r"((r)[3]) : "r"(addr))

#define LDSM_X4_T(r, addr) \
    asm volatile("ldmatrix.sync.aligned.m8n8.x4.trans.shared.b16 {%0,%1,%2,%3}, [%4];" \
        : "=r"((r)[0]), "=r"((r)[1]), "=r"((r)[2]), "=r"((r)[3]) : "r"(addr))

__device__ __forceinline__ void mma_16816(float* d, const uint32_t* a, const uint32_t* b) {
    asm volatile(
        "mma.sync.aligned.m16n8k16.row.col.f32.f16.f16.f32 "
        "{%0,%1,%2,%3}, {%4,%5,%6,%7}, {%8,%9}, {%0,%1,%2,%3};"
        : "+f"(d[0]), "+f"(d[1]), "+f"(d[2]), "+f"(d[3])
        : "r"(a[0]), "r"(a[1]), "r"(a[2]), "r"(a[3]), "r"(b[0]), "r"(b[1]));
}

// ---------------- prep: cos/sin + zero accumulators (single launch) ----------------
__global__ void plv_prep(const float* __restrict__ pa, const float* __restrict__ pb) {
    int idx = blockIdx.x * blockDim.x + threadIdx.x;
    if (idx < BATCH * NA) {
        float s, c;
        sincosf(pa[idx], &s, &c);
        int b = idx >> 13;
        int k = idx & (NA - 1);
        g_A[(size_t)b * NA + k]        = __float2half_rn(c);
        g_A[(size_t)(b + 64) * NA + k] = __float2half_rn(s);
        sincosf(pb[idx], &s, &c);
        g_cb[idx] = c;
        g_sb[idx] = s;
    }
    if (blockIdx.x == 0) {
        if (threadIdx.x < BATCH) { g_real[threadIdx.x] = 0.0f; g_imag[threadIdx.x] = 0.0f; }
        if (threadIdx.x == BATCH) g_npairs = 0u;
    }
}

// ---------------- main: persistent fused mask-stream HMMA GEMM ----------------
__global__ void __launch_bounds__(NTHREADS, 1) plv_main(const int* __restrict__ mask) {
    extern __shared__ char smem_raw[];
    const uint32_t sb = smem_u32(smem_raw);

    const int tid  = threadIdx.x;
    const int wid  = tid >> 5;
    const int lane = tid & 31;
    const int wm   = wid >> 1;     // 0..3 : warp row (32 m each)
    const int wn   = wid & 1;      // 0..1 : warp col (64 n each)

    // static chunk partition: global chunk g = jtile*64 + kchunk
    const int g0 = (int)(((long long)blockIdx.x * NCHUNK) / NCTA);
    const int g1 = (int)(((long long)(blockIdx.x + 1) * NCHUNK) / NCTA);

    float acc[2][8][4];
#pragma unroll
    for (int i = 0; i < 2; ++i)
#pragma unroll
        for (int j = 0; j < 8; ++j)
#pragma unroll
            for (int r = 0; r < 4; ++r) acc[i][j][r] = 0.0f;

    unsigned int msum = 0;

    const uint32_t lrow = (uint32_t)(lane & 15);
    const uint32_t lhi  = (uint32_t)(lane >> 4);

    // ---- A loader (cp.async, fp16 trig straight from gmem); k0 = i offset ----
    auto load_A = [&](int g, int s) {
        const int k0 = (g & 63) * 128;
        const uint32_t dstBase = sb + (uint32_t)s * STAGE;
#pragma unroll
        for (int it = 0; it < 8; ++it) {
            const int idx = tid + it * 256;
            const int m = idx >> 4;
            const int gg = idx & 15;
            cp_async16(dstBase + (uint32_t)m * PITCH_B + (uint32_t)gg * 16,
                       (const char*)g_A + ((size_t)m * NA + (size_t)k0 + (size_t)gg * 8) * 2);
        }
        CP_COMMIT();
    };

    // ---- B loader: 16 x LDG.128 into regs (held during compute) ----
    uint4 breg[16];
    auto load_B = [&](int g) {
        const int k0 = (g & 63) * 128;
        const int j0 = (g >> 6) * 128;
        const int* base = mask + (size_t)k0 * NB + j0;
#pragma unroll
        for (int it = 0; it < 16; ++it) {
            const int idx = tid + it * 256;
            const int k = idx >> 5;
            const int n = (idx & 31) * 4;
            breg[it] = *reinterpret_cast<const uint4*>(base + (size_t)k * NB + n);
        }
    };

    // ---- B convert + STS (stage s): [k][n] fp16 ----
    auto store_B = [&](int s) {
        const uint32_t dstBase = sb + (uint32_t)s * STAGE + TILE_BYTES;
#pragma unroll
        for (int it = 0; it < 16; ++it) {
            const int idx = tid + it * 256;
            const int k = idx >> 5;
            const int n = (idx & 31) * 4;
            const uint4 v = breg[it];
            msum += v.x + v.y + v.z + v.w;
            const uint32_t p0 = (v.x * 0x3C00u) | ((v.y * 0x3C00u) << 16);
            const uint32_t p1 = (v.z * 0x3C00u) | ((v.w * 0x3C00u) << 16);
            asm volatile("st.shared.v2.b32 [%0], {%1, %2};"
                :: "r"(dstBase + (uint32_t)k * PITCH_B + (uint32_t)n * 2), "r"(p0), "r"(p1)
                : "memory");
        }
    };

    // ---- compute one chunk from stage s ----
    auto compute = [&](int s) {
        const uint32_t aBase = sb + (uint32_t)s * STAGE + (uint32_t)(wm * 32) * PITCH_B
                             + lrow * PITCH_B + lhi * 16;
        const uint32_t bBase = sb + (uint32_t)s * STAGE + TILE_BYTES + (uint32_t)(wn * 64) * 2
                             + lrow * PITCH_B + lhi * 16;
#pragma unroll
        for (int ks = 0; ks < 8; ++ks) {
            uint32_t afr[2][4];
            LDSM_X4(afr[0], aBase + (uint32_t)ks * 32);
            LDSM_X4(afr[1], aBase + 16u * PITCH_B + (uint32_t)ks * 32);
            uint32_t bfr[4][4];
#pragma unroll
            for (int nj = 0; nj < 4; ++nj)
                LDSM_X4_T(bfr[nj], bBase + (uint32_t)ks * 16 * PITCH_B + (uint32_t)nj * 32);
#pragma unroll
            for (int mi = 0; mi < 2; ++mi)
#pragma unroll
                for (int nj = 0; nj < 4; ++nj) {
                    mma_16816(acc[mi][nj * 2 + 0], afr[mi], &bfr[nj][0]);
                    mma_16816(acc[mi][nj * 2 + 1], afr[mi], &bfr[nj][2]);
                }
        }
    };

    // ---- flush: fused cb/sb epilogue for j-tile jt, then reset acc ----
    float* cbs    = reinterpret_cast<float*>(smem_raw);            // reuses stage area
    float* sbs    = cbs + 64 * CB_PITCH;
    float* real_s = reinterpret_cast<float*>(smem_raw + ACC_OFF);
    float* imag_s = real_s + 64;
    const int tq = lane >> 2;
    const int tc = (lane & 3) * 2;

    auto flush = [&](int jt) {
        const int j0 = jt * 128;
        if (tid < 64) { real_s[tid] = 0.0f; imag_s[tid] = 0.0f; }
#pragma unroll
        for (int it = 0; it < 32; ++it) {
            const int idx = tid + it * 256;
            const int b = idx >> 7;
            const int n = idx & 127;
            cbs[b * CB_PITCH + n] = g_cb[(size_t)b * NB + j0 + n];
            sbs[b * CB_PITCH + n] = g_sb[(size_t)b * NB + j0 + n];
        }
        __syncthreads();

        const bool isCos = (wm < 2);
#pragma unroll
        for (int mi = 0; mi < 2; ++mi) {
#pragma unroll
            for (int h = 0; h < 2; ++h) {
                const int m = wm * 32 + mi * 16 + h * 8 + tq;
                const int b = m & 63;
                float racc = 0.0f, iacc = 0.0f;
#pragma unroll
                for (int ni = 0; ni < 8; ++ni) {
                    const int n = wn * 64 + ni * 8 + tc;
                    const float dlo = acc[mi][ni][h * 2 + 0];
                    const float dhi = acc[mi][ni][h * 2 + 1];
                    const float2 cv = *reinterpret_cast<const float2*>(&cbs[b * CB_PITCH + n]);
                    const float2 sv = *reinterpret_cast<const float2*>(&sbs[b * CB_PITCH + n]);
                    if (isCos) {
                        racc = fmaf(dlo, cv.x, fmaf(dhi, cv.y, racc));
                        iacc = fmaf(-dlo, sv.x, fmaf(-dhi, sv.y, iacc));
                    } else {
                        racc = fmaf(dlo, sv.x, fmaf(dhi, sv.y, racc));
                        iacc = fmaf(dlo, cv.x, fmaf(dhi, cv.y, iacc));
                    }
                }
                atomicAdd(&real_s[b], racc);
                atomicAdd(&imag_s[b], iacc);
            }
        }
        __syncthreads();
        if (tid < 64) {
            atomicAdd(&g_real[tid], real_s[tid]);
            atomicAdd(&g_imag[tid], imag_s[tid]);
        }
        __syncthreads();   // cbs/sbs (stage region) free before next run's cp.async
#pragma unroll
        for (int i = 0; i < 2; ++i)
#pragma unroll
            for (int j = 0; j < 8; ++j)
#pragma unroll
                for (int r = 0; r < 4; ++r) acc[i][j][r] = 0.0f;
    };

    // ---------------- persistent chunk runs ----------------
    int g = g0;
    while (g < g1) {
        const int jt   = g >> 6;
        const int gend = min(g1, (jt + 1) * NKC);
        const int nrun = gend - g;

        // prologue: fill stage 0 for chunk g
        load_A(g, 0);
        load_B(g);
        store_B(0);
        CP_WAIT0();
        __syncthreads();

        for (int k = 0; k < nrun; ++k) {
            const int s = k & 1;
            if (k + 1 < nrun) {
                load_B(g + k + 1);          // LDGs in flight during compute
                load_A(g + k + 1, s ^ 1);
            }
            compute(s);
            if (k + 1 < nrun) {
                store_B(s ^ 1);
                CP_WAIT0();
            }
            __syncthreads();
        }

        flush(jt);
        g = gend;
    }

    // ---- n_pairs reduce (each mask element converted exactly once globally) ----
#pragma unroll
    for (int o = 16; o; o >>= 1) msum += __shfl_down_sync(0xFFFFFFFFu, msum, o);
    if (lane == 0) atomicAdd(&g_npairs, msum);
}

// ---------------- final ----------------
__global__ void plv_final(float* __restrict__ out) {
    const int b = threadIdx.x;
    if (b < BATCH) {
        const float np = fmaxf((float)g_npairs, 1.0f);
        const float r = g_real[b], i = g_imag[b];
        out[b] = sqrtf(r * r + i * i) / np;
    }
}

// ---------------- launch ----------------
extern "C" void kernel_launch(void* const* d_in, const int* in_sizes, int n_in,
                              void* d_out, int out_size) {
    (void)in_sizes; (void)n_in; (void)out_size;
    const float* pa = (const float*)d_in[0];
    const float* pb = (const float*)d_in[1];
    const int* mask = (const int*)d_in[2];
    float* out      = (float*)d_out;

    cudaFuncSetAttribute(plv_main, cudaFuncAttributeMaxDynamicSharedMemorySize, SMEM_BYTES);

    plv_prep<<<(BATCH * NA + 255) / 256, 256>>>(pa, pb);
    plv_main<<<NCTA, NTHREADS, SMEM_BYTES>>>(mask);
    plv_final<<<1, 64>>>(out);
}